// round 5
// baseline (speedup 1.0000x reference)
#include <cuda_runtime.h>
#include <math.h>

#define NMAX 100000
#define EMAX 1600000

// ---------------- static device scratch ------------------------------------
__device__ __align__(16) float g_bufA[NMAX * 128];   // ping
__device__ __align__(16) float g_bufB[NMAX * 128];   // pong
__device__ int   g_col[EMAX];
__device__ int   g_rowptr[NMAX + 1];
__device__ int   g_cursor[NMAX];
__device__ int   g_outdeg[NMAX];
__device__ int   g_indeg[NMAX];
__device__ float g_norm_src[NMAX];
__device__ float g_norm_dst[NMAX];
__device__ int   g_bsums[128];
__device__ int   g_is64;

// ---------------- preprocessing ---------------------------------------------

// zero degrees; block 0 / thread 0 also probes edge dtype (int32 vs int64)
__global__ void k_zero(const void* ei, int E, int n) {
    int i = blockIdx.x * blockDim.x + threadIdx.x;
    if (i < n) { g_outdeg[i] = 0; g_indeg[i] = 0; }
    if (blockIdx.x == 0 && threadIdx.x == 0) {
        const unsigned long long* p = (const unsigned long long*)ei;
        int cnt = E < 256 ? E : 256;
        int nz = 0;
        for (int k = 0; k < cnt; k++)
            if ((p[k] >> 32) != 0ULL) nz++;
        g_is64 = (nz == 0) ? 1 : 0;
    }
}

__device__ __forceinline__ int edge_at(const void* ei, int E, int which, int e) {
    if (g_is64) return (int)((const long long*)ei)[(size_t)which * E + e];
    return ((const int*)ei)[which * E + e];
}

__global__ void k_degree(const void* __restrict__ ei, int E) {
    int e = blockIdx.x * blockDim.x + threadIdx.x;
    if (e < E) {
        atomicAdd(&g_outdeg[edge_at(ei, E, 0, e)], 1);
        atomicAdd(&g_indeg[edge_at(ei, E, 1, e)], 1);
    }
}

// local exclusive scan of indeg + block sums + degree norms (merged)
__global__ void k_scan_norm(int n) {
    __shared__ int s[2][1024];
    int t = threadIdx.x;
    int i = blockIdx.x * 1024 + t;
    int v = (i < n) ? g_indeg[i] : 0;
    s[0][t] = v;
    __syncthreads();
    int pin = 0;
    #pragma unroll
    for (int off = 1; off < 1024; off <<= 1) {
        int po = pin ^ 1;
        int val = s[pin][t];
        if (t >= off) val += s[pin][t - off];
        s[po][t] = val;
        __syncthreads();
        pin = po;
    }
    int incl = s[pin][t];
    if (i < n) g_rowptr[i] = incl - v;
    if (t == 1023) g_bsums[blockIdx.x] = incl;
    if (i < n) {
        int od = g_outdeg[i];
        g_norm_src[i] = od > 0 ? rsqrtf((float)od) : 0.0f;
        g_norm_dst[i] = v  > 0 ? rsqrtf((float)v)  : 0.0f;
    }
}

// add block-prefix (computed per-block by thread 0) + init cursors
__global__ void k_scan_add(int n, int E) {
    __shared__ int s_off;
    int i = blockIdx.x * blockDim.x + threadIdx.x;
    if (threadIdx.x == 0) {
        int b = (blockIdx.x * blockDim.x) >> 10;   // 256 | 1024, constant per block
        int off = 0;
        for (int k = 0; k < b; k++) off += g_bsums[k];
        s_off = off;
    }
    __syncthreads();
    if (i < n) {
        int r = g_rowptr[i] + s_off;
        g_rowptr[i] = r;
        g_cursor[i] = r;
    }
    if (i == 0) g_rowptr[n] = E;
}

__global__ void k_fill(const void* __restrict__ ei, int E) {
    int e = blockIdx.x * blockDim.x + threadIdx.x;
    if (e < E) {
        int d = edge_at(ei, E, 1, e);
        int pos = atomicAdd(&g_cursor[d], 1);
        g_col[pos] = edge_at(ei, E, 0, e);
    }
}

// buffer selector resolved on device
__device__ __forceinline__ const float* sel_in(int s, const float* ext) {
    return s == 0 ? ext : (s == 1 ? g_bufA : g_bufB);
}
__device__ __forceinline__ float* sel_out(int s, float* ext) {
    return s == 0 ? ext : (s == 1 ? g_bufA : g_bufB);
}

// ---------------- fused layer kernel ----------------------------------------
// Per block: 64 dst nodes.
//   phase 1: z[d,:] = sum_{s in N(d)} (NORM_IN ? norm_src[s] : 1) * X[s,:]  -> smem
//   phase 2: out[d,:] = post( norm_dst[d] * (z @ W) + b )
//            post = tanh (if ACT), then * norm_src[d] (if PRESCALE, feeding next layer)
// Input dim fixed at 128. DOUT = 128 or 64.
template <int DOUT, bool ACT, bool NORM_IN, bool PRESCALE>
__global__ void __launch_bounds__(256) k_layer(
    int inSel, const float* __restrict__ Xext,
    const float* __restrict__ W, const float* __restrict__ bias,
    int outSel, float* __restrict__ outExt, int n)
{
    const float* __restrict__ X = sel_in(inSel, Xext);
    float* __restrict__ out = sel_out(outSel, outExt);

    constexpr int TN = DOUT / 32;                // 4 or 2
    __shared__ __align__(16) float Zs[64 * 128]; // 32 KB
    __shared__ __align__(16) float Ws[32 * DOUT];// 16/8 KB

    int tid  = threadIdx.x;
    int lane = tid & 31;
    int wrp  = tid >> 5;
    int rows0 = blockIdx.x * 64;

    // ---------- phase 1: gather-aggregate into Zs ----------
    #pragma unroll 1
    for (int i = 0; i < 8; i++) {
        int node = rows0 + wrp * 8 + i;
        float4 acc = make_float4(0.f, 0.f, 0.f, 0.f);
        if (node < n) {
            int beg = g_rowptr[node];
            int end = g_rowptr[node + 1];
            for (int e = beg; e < end; e += 32) {
                int m = end - e; if (m > 32) m = 32;
                int idx = (lane < m) ? g_col[e + lane] : 0;
                float ns = 0.f;
                if (NORM_IN) ns = (lane < m) ? g_norm_src[idx] : 0.f;
                for (int j = 0; j < m; j++) {
                    int s = __shfl_sync(0xffffffffu, idx, j);
                    float4 v = *(const float4*)&X[(size_t)s * 128 + lane * 4];
                    if (NORM_IN) {
                        float f = __shfl_sync(0xffffffffu, ns, j);
                        acc.x = fmaf(f, v.x, acc.x);
                        acc.y = fmaf(f, v.y, acc.y);
                        acc.z = fmaf(f, v.z, acc.z);
                        acc.w = fmaf(f, v.w, acc.w);
                    } else {
                        acc.x += v.x; acc.y += v.y;
                        acc.z += v.z; acc.w += v.w;
                    }
                }
            }
        }
        *(float4*)&Zs[(wrp * 8 + i) * 128 + lane * 4] = acc;
    }
    __syncthreads();

    // ---------- phase 2: Zs[64x128] @ W[128xDOUT] ----------
    float acc[8][TN];
    #pragma unroll
    for (int m = 0; m < 8; m++)
        #pragma unroll
        for (int c = 0; c < TN; c++) acc[m][c] = 0.0f;

    for (int kc = 0; kc < 128; kc += 32) {
        {
            const float4* src = (const float4*)(W + kc * DOUT);
            float4* dst = (float4*)Ws;
            #pragma unroll
            for (int q = tid; q < 32 * DOUT / 4; q += 256) dst[q] = src[q];
        }
        __syncthreads();

        #pragma unroll
        for (int kk = 0; kk < 32; kk++) {
            float a[8];
            #pragma unroll
            for (int m = 0; m < 8; m++)
                a[m] = Zs[(wrp * 8 + m) * 128 + kc + kk];   // broadcast LDS
            float b[TN];
            if (TN == 4) {
                float4 bv = *(const float4*)&Ws[kk * DOUT + lane * 4];
                b[0] = bv.x; b[1] = bv.y; b[2] = bv.z; b[3] = bv.w;
            } else {
                float2 bv = *(const float2*)&Ws[kk * DOUT + lane * 2];
                b[0] = bv.x; b[1] = bv.y;
            }
            #pragma unroll
            for (int m = 0; m < 8; m++)
                #pragma unroll
                for (int c = 0; c < TN; c++)
                    acc[m][c] = fmaf(a[m], b[c], acc[m][c]);
        }
        __syncthreads();
    }

    // ---------- epilogue ----------
    #pragma unroll
    for (int m = 0; m < 8; m++) {
        int row = rows0 + wrp * 8 + m;
        if (row < n) {
            float nd = g_norm_dst[row];
            float ps = PRESCALE ? g_norm_src[row] : 1.0f;
            if (TN == 4) {
                float4 bb = *(const float4*)&bias[lane * 4];
                float4 r;
                r.x = fmaf(acc[m][0], nd, bb.x);
                r.y = fmaf(acc[m][1], nd, bb.y);
                r.z = fmaf(acc[m][2], nd, bb.z);
                r.w = fmaf(acc[m][3], nd, bb.w);
                if (ACT) { r.x = tanhf(r.x); r.y = tanhf(r.y);
                           r.z = tanhf(r.z); r.w = tanhf(r.w); }
                r.x *= ps; r.y *= ps; r.z *= ps; r.w *= ps;
                *(float4*)&out[(size_t)row * DOUT + lane * 4] = r;
            } else {
                float2 bb = *(const float2*)&bias[lane * 2];
                float2 r;
                r.x = fmaf(acc[m][0], nd, bb.x);
                r.y = fmaf(acc[m][1], nd, bb.y);
                if (ACT) { r.x = tanhf(r.x); r.y = tanhf(r.y); }
                r.x *= ps; r.y *= ps;
                *(float2*)&out[(size_t)row * DOUT + lane * 2] = r;
            }
        }
    }
}

// ---------------- launch ----------------------------------------------------

extern "C" void kernel_launch(void* const* d_in, const int* in_sizes, int n_in,
                              void* d_out, int out_size)
{
    const float* feat = (const float*)d_in[0];
    const void*  ei   = d_in[1];
    const float* W0 = (const float*)d_in[2]; const float* b0 = (const float*)d_in[3];
    const float* W1 = (const float*)d_in[4]; const float* b1 = (const float*)d_in[5];
    const float* W2 = (const float*)d_in[6]; const float* b2 = (const float*)d_in[7];
    const float* W3 = (const float*)d_in[8]; const float* b3 = (const float*)d_in[9];

    int N = in_sizes[0] / 128;
    int E = in_sizes[1] / 2;
    float* out = (float*)d_out;

    // ---- preprocessing: 5 launches (so launch #6 = fused layer 0 for ncu) ----
    k_zero     <<<(N + 255) / 256, 256>>>(ei, E, N);
    k_degree   <<<(E + 255) / 256, 256>>>(ei, E);
    int nb = (N + 1023) / 1024;
    k_scan_norm<<<nb, 1024>>>(N);
    k_scan_add <<<(N + 255) / 256, 256>>>(N, E);
    k_fill     <<<(E + 255) / 256, 256>>>(ei, E);

    int grid = (N + 63) / 64;

    // selectors: 0 = external, 1 = g_bufA, 2 = g_bufB
    // L0: feat -> A   (norm_src gathered inline; output prescaled by norm_src)
    k_layer<128, true,  true,  true ><<<grid, 256>>>(0, feat, W0, b0, 1, nullptr, N);
    // L1: A -> B
    k_layer<128, true,  false, true ><<<grid, 256>>>(1, nullptr, W1, b1, 2, nullptr, N);
    // L2: B -> A
    k_layer<128, true,  false, true ><<<grid, 256>>>(2, nullptr, W2, b2, 1, nullptr, N);
    // L3: A -> d_out (DOUT=64, no act, no prescale)
    k_layer<64,  false, false, false><<<grid, 256>>>(1, nullptr, W3, b3, 0, out, N);
}

// round 6
// speedup vs baseline: 1.1112x; 1.1112x over previous
#include <cuda_runtime.h>
#include <cuda_bf16.h>
#include <mma.h>
#include <math.h>

using namespace nvcuda;

#define NMAX 100000
#define EMAX 1600000

// ---------------- static device scratch ------------------------------------
__device__ __align__(16) float g_bufA[NMAX * 128];   // ping
__device__ __align__(16) float g_bufB[NMAX * 128];   // pong
__device__ int   g_col[EMAX];
__device__ int   g_rowptr[NMAX + 1];
__device__ int   g_cursor[NMAX];
__device__ int   g_outdeg[NMAX];
__device__ int   g_indeg[NMAX];
__device__ float g_norm_src[NMAX];
__device__ float g_norm_dst[NMAX];
__device__ int   g_bsums[128];
__device__ int   g_is64;
// W split into bf16 hi/lo, TRANSPOSED to [n][k] (k=0..127), per-layer bases 0/16384/32768/49152
__device__ __align__(16) __nv_bfloat16 g_wt_hi[57344];
__device__ __align__(16) __nv_bfloat16 g_wt_lo[57344];

// ---------------- preprocessing ---------------------------------------------

// zero degrees + edge-dtype probe + W transpose/split (extra blocks)
__global__ void k_zero(const void* ei, int E, int n,
                       const float* __restrict__ W0, const float* __restrict__ W1,
                       const float* __restrict__ W2, const float* __restrict__ W3)
{
    int nodeBlocks = (n + 255) >> 8;
    int b = blockIdx.x;
    if (b < nodeBlocks) {
        int i = b * 256 + threadIdx.x;
        if (i < n) { g_outdeg[i] = 0; g_indeg[i] = 0; }
        if (b == 0 && threadIdx.x == 0) {
            const unsigned long long* p = (const unsigned long long*)ei;
            int cnt = E < 256 ? E : 256;
            int nz = 0;
            for (int k = 0; k < cnt; k++)
                if ((p[k] >> 32) != 0ULL) nz++;
            g_is64 = (nz == 0) ? 1 : 0;
        }
    } else {
        int id = (b - nodeBlocks) * 256 + threadIdx.x;
        float w; int dst;
        if (id < 49152) {                       // layers 0-2: W[128][128]
            int layer = id >> 14;
            int rem = id & 16383;
            int k = rem >> 7, nn = rem & 127;
            const float* W = layer == 0 ? W0 : (layer == 1 ? W1 : W2);
            w = W[rem];                          // rem == k*128+nn
            dst = layer * 16384 + nn * 128 + k;
        } else if (id < 57344) {                 // layer 3: W[128][64]
            int rem = id - 49152;
            int k = rem >> 6, nn = rem & 63;
            w = W3[rem];
            dst = 49152 + nn * 128 + k;
        } else return;
        __nv_bfloat16 h = __float2bfloat16(w);
        g_wt_hi[dst] = h;
        g_wt_lo[dst] = __float2bfloat16(w - __bfloat162float(h));
    }
}

__device__ __forceinline__ int edge_at(const void* ei, int E, int which, int e) {
    if (g_is64) return (int)((const long long*)ei)[(size_t)which * E + e];
    return ((const int*)ei)[which * E + e];
}

__global__ void k_degree(const void* __restrict__ ei, int E) {
    int e = blockIdx.x * blockDim.x + threadIdx.x;
    if (e < E) {
        atomicAdd(&g_outdeg[edge_at(ei, E, 0, e)], 1);
        atomicAdd(&g_indeg[edge_at(ei, E, 1, e)], 1);
    }
}

__global__ void k_scan_norm(int n) {
    __shared__ int s[2][1024];
    int t = threadIdx.x;
    int i = blockIdx.x * 1024 + t;
    int v = (i < n) ? g_indeg[i] : 0;
    s[0][t] = v;
    __syncthreads();
    int pin = 0;
    #pragma unroll
    for (int off = 1; off < 1024; off <<= 1) {
        int po = pin ^ 1;
        int val = s[pin][t];
        if (t >= off) val += s[pin][t - off];
        s[po][t] = val;
        __syncthreads();
        pin = po;
    }
    int incl = s[pin][t];
    if (i < n) g_rowptr[i] = incl - v;
    if (t == 1023) g_bsums[blockIdx.x] = incl;
    if (i < n) {
        int od = g_outdeg[i];
        g_norm_src[i] = od > 0 ? rsqrtf((float)od) : 0.0f;
        g_norm_dst[i] = v  > 0 ? rsqrtf((float)v)  : 0.0f;
    }
}

__global__ void k_scan_add(int n, int E) {
    __shared__ int s_off;
    int i = blockIdx.x * blockDim.x + threadIdx.x;
    if (threadIdx.x == 0) {
        int b = (blockIdx.x * blockDim.x) >> 10;
        int off = 0;
        for (int k = 0; k < b; k++) off += g_bsums[k];
        s_off = off;
    }
    __syncthreads();
    if (i < n) {
        int r = g_rowptr[i] + s_off;
        g_rowptr[i] = r;
        g_cursor[i] = r;
    }
    if (i == 0) g_rowptr[n] = E;
}

__global__ void k_fill(const void* __restrict__ ei, int E) {
    int e = blockIdx.x * blockDim.x + threadIdx.x;
    if (e < E) {
        int d = edge_at(ei, E, 1, e);
        int pos = atomicAdd(&g_cursor[d], 1);
        g_col[pos] = edge_at(ei, E, 0, e);
    }
}

__device__ __forceinline__ const float* sel_in(int s, const float* ext) {
    return s == 0 ? ext : (s == 1 ? g_bufA : g_bufB);
}
__device__ __forceinline__ float* sel_out(int s, float* ext) {
    return s == 0 ? ext : (s == 1 ? g_bufA : g_bufB);
}

// ---------------- tensor-core GEMM: H = diag(norm_src) * X @ W --------------
// Block tile 128 x DOUT, K=128 in 4 chunks of 32. 8 warps as 4(M) x 2(N).
// A = norm_src[row]*X[row,:], split bf16 hi/lo at staging. W pre-split/transposed.
// Product = Ah*Bh + Ah*Bl + Al*Bh (fp32 accum) ~ 1e-5 rel err.
template <int DOUT>
__global__ void __launch_bounds__(256, 2) k_gemm_mma(
    int inSel, const float* __restrict__ Xext,
    int wtBase, int outSel, float* __restrict__ Hext, int n)
{
    const float* __restrict__ X = sel_in(inSel, Xext);
    float* __restrict__ H = sel_out(outSel, Hext);

    constexpr int WN = DOUT / 32;              // n-frags per warp (4 or 2)
    __shared__ __align__(16) __nv_bfloat16 Ah[128 * 32];
    __shared__ __align__(16) __nv_bfloat16 Al[128 * 32];
    __shared__ __align__(16) __nv_bfloat16 Bh[DOUT * 32];
    __shared__ __align__(16) __nv_bfloat16 Bl[DOUT * 32];
    __shared__ __align__(16) float Stage[8 * 256];

    int tid  = threadIdx.x;
    int lane = tid & 31;
    int wrp  = tid >> 5;
    int warp_m = wrp >> 1;                     // 0..3
    int warp_n = wrp & 1;                      // 0..1
    int rows0 = blockIdx.x * 128;

    wmma::fragment<wmma::matrix_a, 16, 16, 16, __nv_bfloat16, wmma::row_major> fa_hi[2], fa_lo[2];
    wmma::fragment<wmma::matrix_b, 16, 16, 16, __nv_bfloat16, wmma::col_major> fb_hi, fb_lo;
    wmma::fragment<wmma::accumulator, 16, 16, 16, float> facc[2][WN];
    #pragma unroll
    for (int fm = 0; fm < 2; fm++)
        #pragma unroll
        for (int fn = 0; fn < WN; fn++) wmma::fill_fragment(facc[fm][fn], 0.0f);

    const __nv_bfloat16* gh = g_wt_hi + wtBase;
    const __nv_bfloat16* gl = g_wt_lo + wtBase;

    for (int kc = 0; kc < 128; kc += 32) {
        // stage A (convert fp32 -> bf16 hi/lo, scale by norm_src)
        #pragma unroll
        for (int u = 0; u < 4; u++) {
            int q = tid + 256 * u;             // 0..1023
            int row = q >> 3;
            int kq = q & 7;
            int grow = rows0 + row;
            float4 v = make_float4(0.f, 0.f, 0.f, 0.f);
            float ns = 0.f;
            if (grow < n) {
                ns = g_norm_src[grow];
                v = *(const float4*)&X[(size_t)grow * 128 + kc + kq * 4];
            }
            float xs[4] = {v.x * ns, v.y * ns, v.z * ns, v.w * ns};
            #pragma unroll
            for (int j = 0; j < 4; j++) {
                __nv_bfloat16 h = __float2bfloat16(xs[j]);
                Ah[row * 32 + kq * 4 + j] = h;
                Al[row * 32 + kq * 4 + j] = __float2bfloat16(xs[j] - __bfloat162float(h));
            }
        }
        // stage B (copy pre-split bf16, 2 bf16 per uint)
        for (int q = tid; q < DOUT * 16; q += 256) {
            int rn = q >> 4;
            int k2 = q & 15;
            ((unsigned*)Bh)[q] = ((const unsigned*)gh)[rn * 64 + (kc >> 1) + k2];
            ((unsigned*)Bl)[q] = ((const unsigned*)gl)[rn * 64 + (kc >> 1) + k2];
        }
        __syncthreads();

        #pragma unroll
        for (int kk = 0; kk < 32; kk += 16) {
            #pragma unroll
            for (int fm = 0; fm < 2; fm++) {
                wmma::load_matrix_sync(fa_hi[fm], &Ah[(warp_m * 32 + fm * 16) * 32 + kk], 32);
                wmma::load_matrix_sync(fa_lo[fm], &Al[(warp_m * 32 + fm * 16) * 32 + kk], 32);
            }
            #pragma unroll
            for (int fn = 0; fn < WN; fn++) {
                int nb = (warp_n * (DOUT / 2) + fn * 16) * 32 + kk;
                wmma::load_matrix_sync(fb_hi, &Bh[nb], 32);
                wmma::load_matrix_sync(fb_lo, &Bl[nb], 32);
                #pragma unroll
                for (int fm = 0; fm < 2; fm++) {
                    wmma::mma_sync(facc[fm][fn], fa_hi[fm], fb_hi, facc[fm][fn]);
                    wmma::mma_sync(facc[fm][fn], fa_hi[fm], fb_lo, facc[fm][fn]);
                    wmma::mma_sync(facc[fm][fn], fa_lo[fm], fb_hi, facc[fm][fn]);
                }
            }
        }
        __syncthreads();
    }

    // epilogue
    if (rows0 + 128 <= n) {
        #pragma unroll
        for (int fm = 0; fm < 2; fm++)
            #pragma unroll
            for (int fn = 0; fn < WN; fn++)
                wmma::store_matrix_sync(
                    H + (size_t)(rows0 + warp_m * 32 + fm * 16) * DOUT
                      + warp_n * (DOUT / 2) + fn * 16,
                    facc[fm][fn], DOUT, wmma::mem_row_major);
    } else {
        float* st = &Stage[wrp * 256];
        #pragma unroll
        for (int fm = 0; fm < 2; fm++)
            #pragma unroll
            for (int fn = 0; fn < WN; fn++) {
                wmma::store_matrix_sync(st, facc[fm][fn], 16, wmma::mem_row_major);
                __syncwarp();
                int rbase = rows0 + warp_m * 32 + fm * 16;
                int cbase = warp_n * (DOUT / 2) + fn * 16;
                for (int q = lane; q < 256; q += 32) {
                    int r = q >> 4, c = q & 15;
                    int gr = rbase + r;
                    if (gr < n) H[(size_t)gr * DOUT + cbase + c] = st[q];
                }
                __syncwarp();
            }
    }
}

// ---------------- sparse aggregation (one warp per dst, R4 version) ---------
template <int D, bool ACT>
__global__ void __launch_bounds__(256) k_agg(
    int inSel, const float* __restrict__ Hext,
    const float* __restrict__ bias,
    int outSel, float* __restrict__ outExt, int n)
{
    const float* __restrict__ H = sel_in(inSel, Hext);
    float* __restrict__ out = sel_out(outSel, outExt);

    int gw = (blockIdx.x * blockDim.x + threadIdx.x) >> 5;
    int lane = threadIdx.x & 31;
    if (gw >= n) return;

    int beg = g_rowptr[gw];
    int end = g_rowptr[gw + 1];
    float4 acc = make_float4(0.f, 0.f, 0.f, 0.f);
    const bool active = lane < D / 4;

    for (int e = beg; e < end; e += 32) {
        int m = end - e; if (m > 32) m = 32;
        int idx = (lane < m) ? g_col[e + lane] : 0;
        for (int j = 0; j < m; j++) {
            int s = __shfl_sync(0xffffffffu, idx, j);
            if (active) {
                float4 v = *(const float4*)&H[(size_t)s * D + lane * 4];
                acc.x += v.x; acc.y += v.y; acc.z += v.z; acc.w += v.w;
            }
        }
    }

    if (active) {
        float nd = g_norm_dst[gw];
        float4 bb = *(const float4*)&bias[lane * 4];
        float4 r;
        r.x = fmaf(acc.x, nd, bb.x);
        r.y = fmaf(acc.y, nd, bb.y);
        r.z = fmaf(acc.z, nd, bb.z);
        r.w = fmaf(acc.w, nd, bb.w);
        if (ACT) {
            r.x = tanhf(r.x); r.y = tanhf(r.y);
            r.z = tanhf(r.z); r.w = tanhf(r.w);
        }
        *(float4*)&out[(size_t)gw * D + lane * 4] = r;
    }
}

// ---------------- launch ----------------------------------------------------

extern "C" void kernel_launch(void* const* d_in, const int* in_sizes, int n_in,
                              void* d_out, int out_size)
{
    const float* feat = (const float*)d_in[0];
    const void*  ei   = d_in[1];
    const float* W0 = (const float*)d_in[2]; const float* b0 = (const float*)d_in[3];
    const float* W1 = (const float*)d_in[4]; const float* b1 = (const float*)d_in[5];
    const float* W2 = (const float*)d_in[6]; const float* b2 = (const float*)d_in[7];
    const float* W3 = (const float*)d_in[8]; const float* b3 = (const float*)d_in[9];

    int N = in_sizes[0] / 128;
    int E = in_sizes[1] / 2;
    float* out = (float*)d_out;

    int nodeBlocks = (N + 255) / 256;
    int wBlocks = (57344 + 255) / 256;

    // #1..#3: everything gemm0 needs (norm_src)
    k_zero     <<<nodeBlocks + wBlocks, 256>>>(ei, E, N, W0, W1, W2, W3);
    k_degree   <<<(E + 255) / 256, 256>>>(ei, E);
    k_scan_norm<<<(N + 1023) / 1024, 1024>>>(N);

    int gemmGrid = (N + 127) / 128;
    int aggGrid  = (N * 32 + 255) / 256;

    // #4: layer-0 GEMM (profiled launch)
    k_gemm_mma<128><<<gemmGrid, 256>>>(0, feat, 0, 2, nullptr, N);

    // #5,#6: finish CSR (needed only by k_agg)
    k_scan_add<<<(N + 255) / 256, 256>>>(N, E);
    k_fill    <<<(E + 255) / 256, 256>>>(ei, E);

    // remaining layers
    k_agg<128, true><<<aggGrid, 256>>>(2, nullptr, b0, 1, nullptr, N);
    k_gemm_mma<128><<<gemmGrid, 256>>>(1, nullptr, 16384, 2, nullptr, N);
    k_agg<128, true><<<aggGrid, 256>>>(2, nullptr, b1, 1, nullptr, N);
    k_gemm_mma<128><<<gemmGrid, 256>>>(1, nullptr, 32768, 2, nullptr, N);
    k_agg<128, true><<<aggGrid, 256>>>(2, nullptr, b2, 1, nullptr, N);
    k_gemm_mma<64><<<gemmGrid, 256>>>(1, nullptr, 49152, 2, nullptr, N);
    k_agg<64, false><<<aggGrid, 256>>>(2, nullptr, b3, 0, out, N);
}

// round 7
// speedup vs baseline: 1.2243x; 1.1018x over previous
#include <cuda_runtime.h>
#include <cuda_bf16.h>
#include <mma.h>
#include <math.h>

using namespace nvcuda;

#define NMAX 100000
#define EMAX 1600000

// ---------------- static device scratch ------------------------------------
__device__ __align__(16) float g_bufA[NMAX * 128];   // ping
__device__ __align__(16) float g_bufB[NMAX * 128];   // pong
__device__ int   g_col[EMAX];
__device__ int   g_rowptr[NMAX + 1];
__device__ int   g_cursor[NMAX];
__device__ int   g_outdeg[NMAX];
__device__ int   g_indeg[NMAX];
__device__ float g_norm_src[NMAX];
__device__ float g_norm_dst[NMAX];
__device__ int   g_bsums[128];
__device__ int   g_is64;
// W split into bf16 hi/lo, TRANSPOSED to [n][k], per-layer bases 0/16384/32768/49152
__device__ __align__(16) __nv_bfloat16 g_wt_hi[57344];
__device__ __align__(16) __nv_bfloat16 g_wt_lo[57344];

// ---------------- preprocessing ---------------------------------------------

__global__ void k_zero(const void* ei, int E, int n,
                       const float* __restrict__ W0, const float* __restrict__ W1,
                       const float* __restrict__ W2, const float* __restrict__ W3)
{
    int nodeBlocks = (n + 255) >> 8;
    int b = blockIdx.x;
    if (b < nodeBlocks) {
        int i = b * 256 + threadIdx.x;
        if (i < n) { g_outdeg[i] = 0; g_indeg[i] = 0; }
        if (b == 0 && threadIdx.x == 0) {
            const unsigned long long* p = (const unsigned long long*)ei;
            int cnt = E < 256 ? E : 256;
            int nz = 0;
            for (int k = 0; k < cnt; k++)
                if ((p[k] >> 32) != 0ULL) nz++;
            g_is64 = (nz == 0) ? 1 : 0;
        }
    } else {
        int id = (b - nodeBlocks) * 256 + threadIdx.x;
        float w; int dst;
        if (id < 49152) {                       // layers 0-2: W[128][128]
            int layer = id >> 14;
            int rem = id & 16383;
            int k = rem >> 7, nn = rem & 127;
            const float* W = layer == 0 ? W0 : (layer == 1 ? W1 : W2);
            w = W[rem];
            dst = layer * 16384 + nn * 128 + k;
        } else if (id < 57344) {                 // layer 3: W[128][64]
            int rem = id - 49152;
            int k = rem >> 6, nn = rem & 63;
            w = W3[rem];
            dst = 49152 + nn * 128 + k;
        } else return;
        __nv_bfloat16 h = __float2bfloat16(w);
        g_wt_hi[dst] = h;
        g_wt_lo[dst] = __float2bfloat16(w - __bfloat162float(h));
    }
}

__device__ __forceinline__ int edge_at(const void* ei, int E, int which, int e) {
    if (g_is64) return (int)((const long long*)ei)[(size_t)which * E + e];
    return ((const int*)ei)[which * E + e];
}

__global__ void k_degree(const void* __restrict__ ei, int E) {
    int e = blockIdx.x * blockDim.x + threadIdx.x;
    if (e < E) {
        atomicAdd(&g_outdeg[edge_at(ei, E, 0, e)], 1);
        atomicAdd(&g_indeg[edge_at(ei, E, 1, e)], 1);
    }
}

__global__ void k_scan_norm(int n) {
    __shared__ int s[2][1024];
    int t = threadIdx.x;
    int i = blockIdx.x * 1024 + t;
    int v = (i < n) ? g_indeg[i] : 0;
    s[0][t] = v;
    __syncthreads();
    int pin = 0;
    #pragma unroll
    for (int off = 1; off < 1024; off <<= 1) {
        int po = pin ^ 1;
        int val = s[pin][t];
        if (t >= off) val += s[pin][t - off];
        s[po][t] = val;
        __syncthreads();
        pin = po;
    }
    int incl = s[pin][t];
    if (i < n) g_rowptr[i] = incl - v;
    if (t == 1023) g_bsums[blockIdx.x] = incl;
    if (i < n) {
        int od = g_outdeg[i];
        g_norm_src[i] = od > 0 ? rsqrtf((float)od) : 0.0f;
        g_norm_dst[i] = v  > 0 ? rsqrtf((float)v)  : 0.0f;
    }
}

__global__ void k_scan_add(int n, int E) {
    __shared__ int s_off;
    int i = blockIdx.x * blockDim.x + threadIdx.x;
    if (threadIdx.x == 0) {
        int b = (blockIdx.x * blockDim.x) >> 10;
        int off = 0;
        for (int k = 0; k < b; k++) off += g_bsums[k];
        s_off = off;
    }
    __syncthreads();
    if (i < n) {
        int r = g_rowptr[i] + s_off;
        g_rowptr[i] = r;
        g_cursor[i] = r;
    }
    if (i == 0) g_rowptr[n] = E;
}

__global__ void k_fill(const void* __restrict__ ei, int E) {
    int e = blockIdx.x * blockDim.x + threadIdx.x;
    if (e < E) {
        int d = edge_at(ei, E, 1, e);
        int pos = atomicAdd(&g_cursor[d], 1);
        g_col[pos] = edge_at(ei, E, 0, e);
    }
}

__device__ __forceinline__ const float* sel_in(int s, const float* ext) {
    return s == 0 ? ext : (s == 1 ? g_bufA : g_bufB);
}
__device__ __forceinline__ float* sel_out(int s, float* ext) {
    return s == 0 ? ext : (s == 1 ? g_bufA : g_bufB);
}

// ---------------- tensor-core GEMM: H = diag(norm_src) * X @ W --------------
// Block tile 128 x DOUT, K chunks of 32. 8 warps as 4(M) x 2(N).
// Padded smem stride (40 elems, 80B) -> conflict-free LDSM.
// Product = Ah*Bh + Ah*Bl + Al*Bh (fp32 accum).
template <int DOUT>
__global__ void __launch_bounds__(256, 2) k_gemm_mma(
    int inSel, const float* __restrict__ Xext,
    int wtBase, int outSel, float* __restrict__ Hext, int n)
{
    const float* __restrict__ X = sel_in(inSel, Xext);
    float* __restrict__ H = sel_out(outSel, Hext);

    constexpr int WN = DOUT / 32;              // n-frags per warp (4 or 2)
    constexpr int AS = 40;                     // padded row stride (elements)
    __shared__ __align__(16) __nv_bfloat16 Ah[128 * AS];
    __shared__ __align__(16) __nv_bfloat16 Al[128 * AS];
    __shared__ __align__(16) __nv_bfloat16 Bh[DOUT * AS];
    __shared__ __align__(16) __nv_bfloat16 Bl[DOUT * AS];
    __shared__ __align__(16) float Stage[8 * 256];

    int tid  = threadIdx.x;
    int lane = tid & 31;
    int wrp  = tid >> 5;
    int warp_m = wrp >> 1;                     // 0..3
    int warp_n = wrp & 1;                      // 0..1
    int rows0 = blockIdx.x * 128;

    wmma::fragment<wmma::matrix_a, 16, 16, 16, __nv_bfloat16, wmma::row_major> fa_hi[2], fa_lo[2];
    wmma::fragment<wmma::matrix_b, 16, 16, 16, __nv_bfloat16, wmma::col_major> fb_hi, fb_lo;
    wmma::fragment<wmma::accumulator, 16, 16, 16, float> facc[2][WN];
    #pragma unroll
    for (int fm = 0; fm < 2; fm++)
        #pragma unroll
        for (int fn = 0; fn < WN; fn++) wmma::fill_fragment(facc[fm][fn], 0.0f);

    const __nv_bfloat16* gh = g_wt_hi + wtBase;
    const __nv_bfloat16* gl = g_wt_lo + wtBase;

    for (int kc = 0; kc < 128; kc += 32) {
        // stage A: fp32 -> bf16 hi/lo, scaled by norm_src; 8B packed stores
        #pragma unroll
        for (int u = 0; u < 4; u++) {
            int q = tid + 256 * u;             // 0..1023
            int row = q >> 3;
            int kq = q & 7;
            int grow = rows0 + row;
            float4 v = make_float4(0.f, 0.f, 0.f, 0.f);
            float ns = 0.f;
            if (grow < n) {
                ns = g_norm_src[grow];
                v = *(const float4*)&X[(size_t)grow * 128 + kc + kq * 4];
            }
            float xs[4] = {v.x * ns, v.y * ns, v.z * ns, v.w * ns};
            unsigned hw[4], lw[4];
            #pragma unroll
            for (int j = 0; j < 4; j++) {
                __nv_bfloat16 h = __float2bfloat16(xs[j]);
                __nv_bfloat16 l = __float2bfloat16(xs[j] - __bfloat162float(h));
                hw[j] = (unsigned)__bfloat16_as_ushort(h);
                lw[j] = (unsigned)__bfloat16_as_ushort(l);
            }
            uint2 uh = make_uint2(hw[0] | (hw[1] << 16), hw[2] | (hw[3] << 16));
            uint2 ul = make_uint2(lw[0] | (lw[1] << 16), lw[2] | (lw[3] << 16));
            *(uint2*)&Ah[row * AS + kq * 4] = uh;
            *(uint2*)&Al[row * AS + kq * 4] = ul;
        }
        // stage B into padded rows (4B copies of pre-split bf16)
        for (int q = tid; q < DOUT * 16; q += 256) {
            int rn = q >> 4;
            int k2 = q & 15;
            ((unsigned*)Bh)[rn * (AS / 2) + k2] = ((const unsigned*)gh)[rn * 64 + (kc >> 1) + k2];
            ((unsigned*)Bl)[rn * (AS / 2) + k2] = ((const unsigned*)gl)[rn * 64 + (kc >> 1) + k2];
        }
        __syncthreads();

        #pragma unroll
        for (int kk = 0; kk < 32; kk += 16) {
            #pragma unroll
            for (int fm = 0; fm < 2; fm++) {
                wmma::load_matrix_sync(fa_hi[fm], &Ah[(warp_m * 32 + fm * 16) * AS + kk], AS);
                wmma::load_matrix_sync(fa_lo[fm], &Al[(warp_m * 32 + fm * 16) * AS + kk], AS);
            }
            #pragma unroll
            for (int fn = 0; fn < WN; fn++) {
                int nb = (warp_n * (DOUT / 2) + fn * 16) * AS + kk;
                wmma::load_matrix_sync(fb_hi, &Bh[nb], AS);
                wmma::load_matrix_sync(fb_lo, &Bl[nb], AS);
                #pragma unroll
                for (int fm = 0; fm < 2; fm++) {
                    wmma::mma_sync(facc[fm][fn], fa_hi[fm], fb_hi, facc[fm][fn]);
                    wmma::mma_sync(facc[fm][fn], fa_hi[fm], fb_lo, facc[fm][fn]);
                    wmma::mma_sync(facc[fm][fn], fa_lo[fm], fb_hi, facc[fm][fn]);
                }
            }
        }
        __syncthreads();
    }

    // epilogue
    if (rows0 + 128 <= n) {
        #pragma unroll
        for (int fm = 0; fm < 2; fm++)
            #pragma unroll
            for (int fn = 0; fn < WN; fn++)
                wmma::store_matrix_sync(
                    H + (size_t)(rows0 + warp_m * 32 + fm * 16) * DOUT
                      + warp_n * (DOUT / 2) + fn * 16,
                    facc[fm][fn], DOUT, wmma::mem_row_major);
    } else {
        float* st = &Stage[wrp * 256];
        #pragma unroll
        for (int fm = 0; fm < 2; fm++)
            #pragma unroll
            for (int fn = 0; fn < WN; fn++) {
                wmma::store_matrix_sync(st, facc[fm][fn], 16, wmma::mem_row_major);
                __syncwarp();
                int rbase = rows0 + warp_m * 32 + fm * 16;
                int cbase = warp_n * (DOUT / 2) + fn * 16;
                for (int q = lane; q < 256; q += 32) {
                    int r = q >> 4, c = q & 15;
                    int gr = rbase + r;
                    if (gr < n) H[(size_t)gr * DOUT + cbase + c] = st[q];
                }
                __syncwarp();
            }
    }
}

// ---------------- sparse aggregation (one warp per dst) ---------------------
template <int D, bool ACT>
__global__ void __launch_bounds__(256) k_agg(
    int inSel, const float* __restrict__ Hext,
    const float* __restrict__ bias,
    int outSel, float* __restrict__ outExt, int n)
{
    const float* __restrict__ H = sel_in(inSel, Hext);
    float* __restrict__ out = sel_out(outSel, outExt);

    int gw = (blockIdx.x * blockDim.x + threadIdx.x) >> 5;
    int lane = threadIdx.x & 31;
    if (gw >= n) return;

    int beg = g_rowptr[gw];
    int end = g_rowptr[gw + 1];
    float4 acc = make_float4(0.f, 0.f, 0.f, 0.f);
    const bool active = lane < D / 4;

    for (int e = beg; e < end; e += 32) {
        int m = end - e; if (m > 32) m = 32;
        int idx = (lane < m) ? g_col[e + lane] : 0;
        for (int j = 0; j < m; j++) {
            int s = __shfl_sync(0xffffffffu, idx, j);
            if (active) {
                float4 v = *(const float4*)&H[(size_t)s * D + lane * 4];
                acc.x += v.x; acc.y += v.y; acc.z += v.z; acc.w += v.w;
            }
        }
    }

    if (active) {
        float nd = g_norm_dst[gw];
        float4 bb = *(const float4*)&bias[lane * 4];
        float4 r;
        r.x = fmaf(acc.x, nd, bb.x);
        r.y = fmaf(acc.y, nd, bb.y);
        r.z = fmaf(acc.z, nd, bb.z);
        r.w = fmaf(acc.w, nd, bb.w);
        if (ACT) {
            r.x = tanhf(r.x); r.y = tanhf(r.y);
            r.z = tanhf(r.z); r.w = tanhf(r.w);
        }
        *(float4*)&out[(size_t)gw * D + lane * 4] = r;
    }
}

// ---------------- launch ----------------------------------------------------

extern "C" void kernel_launch(void* const* d_in, const int* in_sizes, int n_in,
                              void* d_out, int out_size)
{
    const float* feat = (const float*)d_in[0];
    const void*  ei   = d_in[1];
    const float* W0 = (const float*)d_in[2]; const float* b0 = (const float*)d_in[3];
    const float* W1 = (const float*)d_in[4]; const float* b1 = (const float*)d_in[5];
    const float* W2 = (const float*)d_in[6]; const float* b2 = (const float*)d_in[7];
    const float* W3 = (const float*)d_in[8]; const float* b3 = (const float*)d_in[9];

    int N = in_sizes[0] / 128;
    int E = in_sizes[1] / 2;
    float* out = (float*)d_out;

    int nodeBlocks = (N + 255) / 256;
    int wBlocks = (57344 + 255) / 256;

    // #1..#3: everything gemm0 needs (norm_src)
    k_zero     <<<nodeBlocks + wBlocks, 256>>>(ei, E, N, W0, W1, W2, W3);
    k_degree   <<<(E + 255) / 256, 256>>>(ei, E);
    k_scan_norm<<<(N + 1023) / 1024, 1024>>>(N);

    int gemmGrid = (N + 127) / 128;
    int aggGrid  = (N * 32 + 255) / 256;

    // #4: layer-0 GEMM (profiled launch)
    k_gemm_mma<128><<<gemmGrid, 256>>>(0, feat, 0, 2, nullptr, N);

    // #5,#6: finish CSR (needed only by k_agg)
    k_scan_add<<<(N + 255) / 256, 256>>>(N, E);
    k_fill    <<<(E + 255) / 256, 256>>>(ei, E);

    // remaining layers
    k_agg<128, true><<<aggGrid, 256>>>(2, nullptr, b0, 1, nullptr, N);
    k_gemm_mma<128><<<gemmGrid, 256>>>(1, nullptr, 16384, 2, nullptr, N);
    k_agg<128, true><<<aggGrid, 256>>>(2, nullptr, b1, 1, nullptr, N);
    k_gemm_mma<128><<<gemmGrid, 256>>>(1, nullptr, 32768, 2, nullptr, N);
    k_agg<128, true><<<aggGrid, 256>>>(2, nullptr, b2, 1, nullptr, N);
    k_gemm_mma<64><<<gemmGrid, 256>>>(1, nullptr, 49152, 2, nullptr, N);
    k_agg<64, false><<<aggGrid, 256>>>(2, nullptr, b3, 0, out, N);
}

// round 8
// speedup vs baseline: 1.4365x; 1.1734x over previous
#include <cuda_runtime.h>
#include <cuda_bf16.h>
#include <cuda_fp16.h>
#include <mma.h>
#include <math.h>

using namespace nvcuda;

#define NMAX 100000
#define EMAX 1600000

// ---------------- static device scratch ------------------------------------
__device__ __align__(16) float  g_bufA[NMAX * 128];   // fp32 node features X
__device__ __align__(16) __half g_bufH[NMAX * 128];   // fp16 GEMM output H (gather source)
__device__ int   g_col[EMAX];
__device__ int   g_rowptr[NMAX + 1];
__device__ int   g_cursor[NMAX];
__device__ int   g_outdeg[NMAX];
__device__ int   g_indeg[NMAX];
__device__ float g_norm_src[NMAX];
__device__ float g_norm_dst[NMAX];
__device__ int   g_bsums[128];
__device__ int   g_is64;
// W split into bf16 hi/lo, TRANSPOSED to [n][k], per-layer bases 0/16384/32768/49152
__device__ __align__(16) __nv_bfloat16 g_wt_hi[57344];
__device__ __align__(16) __nv_bfloat16 g_wt_lo[57344];

// ---------------- preprocessing ---------------------------------------------

__global__ void k_zero(const void* ei, int E, int n,
                       const float* __restrict__ W0, const float* __restrict__ W1,
                       const float* __restrict__ W2, const float* __restrict__ W3)
{
    int nodeBlocks = (n + 255) >> 8;
    int b = blockIdx.x;
    if (b < nodeBlocks) {
        int i = b * 256 + threadIdx.x;
        if (i < n) { g_outdeg[i] = 0; g_indeg[i] = 0; }
        if (b == 0 && threadIdx.x == 0) {
            const unsigned long long* p = (const unsigned long long*)ei;
            int cnt = E < 256 ? E : 256;
            int nz = 0;
            for (int k = 0; k < cnt; k++)
                if ((p[k] >> 32) != 0ULL) nz++;
            g_is64 = (nz == 0) ? 1 : 0;
        }
    } else {
        int id = (b - nodeBlocks) * 256 + threadIdx.x;
        float w; int dst;
        if (id < 49152) {                       // layers 0-2: W[128][128]
            int layer = id >> 14;
            int rem = id & 16383;
            int k = rem >> 7, nn = rem & 127;
            const float* W = layer == 0 ? W0 : (layer == 1 ? W1 : W2);
            w = W[rem];
            dst = layer * 16384 + nn * 128 + k;
        } else if (id < 57344) {                 // layer 3: W[128][64]
            int rem = id - 49152;
            int k = rem >> 6, nn = rem & 63;
            w = W3[rem];
            dst = 49152 + nn * 128 + k;
        } else return;
        __nv_bfloat16 h = __float2bfloat16(w);
        g_wt_hi[dst] = h;
        g_wt_lo[dst] = __float2bfloat16(w - __bfloat162float(h));
    }
}

__device__ __forceinline__ int edge_at(const void* ei, int E, int which, int e) {
    if (g_is64) return (int)((const long long*)ei)[(size_t)which * E + e];
    return ((const int*)ei)[which * E + e];
}

__global__ void k_degree(const void* __restrict__ ei, int E) {
    int e = blockIdx.x * blockDim.x + threadIdx.x;
    if (e < E) {
        atomicAdd(&g_outdeg[edge_at(ei, E, 0, e)], 1);
        atomicAdd(&g_indeg[edge_at(ei, E, 1, e)], 1);
    }
}

__global__ void k_scan_norm(int n) {
    __shared__ int s[2][1024];
    int t = threadIdx.x;
    int i = blockIdx.x * 1024 + t;
    int v = (i < n) ? g_indeg[i] : 0;
    s[0][t] = v;
    __syncthreads();
    int pin = 0;
    #pragma unroll
    for (int off = 1; off < 1024; off <<= 1) {
        int po = pin ^ 1;
        int val = s[pin][t];
        if (t >= off) val += s[pin][t - off];
        s[po][t] = val;
        __syncthreads();
        pin = po;
    }
    int incl = s[pin][t];
    if (i < n) g_rowptr[i] = incl - v;
    if (t == 1023) g_bsums[blockIdx.x] = incl;
    if (i < n) {
        int od = g_outdeg[i];
        g_norm_src[i] = od > 0 ? rsqrtf((float)od) : 0.0f;
        g_norm_dst[i] = v  > 0 ? rsqrtf((float)v)  : 0.0f;
    }
}

__global__ void k_scan_add(int n, int E) {
    __shared__ int s_off;
    int i = blockIdx.x * blockDim.x + threadIdx.x;
    if (threadIdx.x == 0) {
        int b = (blockIdx.x * blockDim.x) >> 10;
        int off = 0;
        for (int k = 0; k < b; k++) off += g_bsums[k];
        s_off = off;
    }
    __syncthreads();
    if (i < n) {
        int r = g_rowptr[i] + s_off;
        g_rowptr[i] = r;
        g_cursor[i] = r;
    }
    if (i == 0) g_rowptr[n] = E;
}

__global__ void k_fill(const void* __restrict__ ei, int E) {
    int e = blockIdx.x * blockDim.x + threadIdx.x;
    if (e < E) {
        int d = edge_at(ei, E, 1, e);
        int pos = atomicAdd(&g_cursor[d], 1);
        g_col[pos] = edge_at(ei, E, 0, e);
    }
}

// ---------------- tensor-core GEMM: H(fp16) = diag(norm_src) * X @ W --------
// Block tile 128 x DOUT, K chunks of 32. 8 warps as 4(M) x 2(N).
// Padded smem stride (40 elems) -> conflict-free LDSM.
// Product = Ah*Bh + Ah*Bl + Al*Bh (fp32 accum). Output stored fp16.
template <int DOUT>
__global__ void __launch_bounds__(256, 2) k_gemm_mma(
    int inSel, const float* __restrict__ Xext, int wtBase, int n)
{
    const float* __restrict__ X = (inSel == 0) ? Xext : g_bufA;
    __half* __restrict__ H = g_bufH;

    constexpr int WN = DOUT / 32;              // n-frags per warp (4 or 2)
    constexpr int AS = 40;                     // padded row stride (elements)
    __shared__ __align__(16) __nv_bfloat16 Ah[128 * AS];
    __shared__ __align__(16) __nv_bfloat16 Al[128 * AS];
    __shared__ __align__(16) __nv_bfloat16 Bh[DOUT * AS];
    __shared__ __align__(16) __nv_bfloat16 Bl[DOUT * AS];
    __shared__ __align__(16) float Stage[8 * 256];

    int tid  = threadIdx.x;
    int lane = tid & 31;
    int wrp  = tid >> 5;
    int warp_m = wrp >> 1;                     // 0..3
    int warp_n = wrp & 1;                      // 0..1
    int rows0 = blockIdx.x * 128;

    wmma::fragment<wmma::matrix_a, 16, 16, 16, __nv_bfloat16, wmma::row_major> fa_hi[2], fa_lo[2];
    wmma::fragment<wmma::matrix_b, 16, 16, 16, __nv_bfloat16, wmma::col_major> fb_hi, fb_lo;
    wmma::fragment<wmma::accumulator, 16, 16, 16, float> facc[2][WN];
    #pragma unroll
    for (int fm = 0; fm < 2; fm++)
        #pragma unroll
        for (int fn = 0; fn < WN; fn++) wmma::fill_fragment(facc[fm][fn], 0.0f);

    const __nv_bfloat16* gh = g_wt_hi + wtBase;
    const __nv_bfloat16* gl = g_wt_lo + wtBase;

    for (int kc = 0; kc < 128; kc += 32) {
        // stage A: fp32 -> bf16 hi/lo, scaled by norm_src; 8B packed stores
        #pragma unroll
        for (int u = 0; u < 4; u++) {
            int q = tid + 256 * u;             // 0..1023
            int row = q >> 3;
            int kq = q & 7;
            int grow = rows0 + row;
            float4 v = make_float4(0.f, 0.f, 0.f, 0.f);
            float ns = 0.f;
            if (grow < n) {
                ns = g_norm_src[grow];
                v = *(const float4*)&X[(size_t)grow * 128 + kc + kq * 4];
            }
            float xs[4] = {v.x * ns, v.y * ns, v.z * ns, v.w * ns};
            unsigned hw[4], lw[4];
            #pragma unroll
            for (int j = 0; j < 4; j++) {
                __nv_bfloat16 h = __float2bfloat16(xs[j]);
                __nv_bfloat16 l = __float2bfloat16(xs[j] - __bfloat162float(h));
                hw[j] = (unsigned)__bfloat16_as_ushort(h);
                lw[j] = (unsigned)__bfloat16_as_ushort(l);
            }
            uint2 uh = make_uint2(hw[0] | (hw[1] << 16), hw[2] | (hw[3] << 16));
            uint2 ul = make_uint2(lw[0] | (lw[1] << 16), lw[2] | (lw[3] << 16));
            *(uint2*)&Ah[row * AS + kq * 4] = uh;
            *(uint2*)&Al[row * AS + kq * 4] = ul;
        }
        // stage B into padded rows (4B copies of pre-split bf16)
        for (int q = tid; q < DOUT * 16; q += 256) {
            int rn = q >> 4;
            int k2 = q & 15;
            ((unsigned*)Bh)[rn * (AS / 2) + k2] = ((const unsigned*)gh)[rn * 64 + (kc >> 1) + k2];
            ((unsigned*)Bl)[rn * (AS / 2) + k2] = ((const unsigned*)gl)[rn * 64 + (kc >> 1) + k2];
        }
        __syncthreads();

        #pragma unroll
        for (int kk = 0; kk < 32; kk += 16) {
            #pragma unroll
            for (int fm = 0; fm < 2; fm++) {
                wmma::load_matrix_sync(fa_hi[fm], &Ah[(warp_m * 32 + fm * 16) * AS + kk], AS);
                wmma::load_matrix_sync(fa_lo[fm], &Al[(warp_m * 32 + fm * 16) * AS + kk], AS);
            }
            #pragma unroll
            for (int fn = 0; fn < WN; fn++) {
                int nb = (warp_n * (DOUT / 2) + fn * 16) * AS + kk;
                wmma::load_matrix_sync(fb_hi, &Bh[nb], AS);
                wmma::load_matrix_sync(fb_lo, &Bl[nb], AS);
                #pragma unroll
                for (int fm = 0; fm < 2; fm++) {
                    wmma::mma_sync(facc[fm][fn], fa_hi[fm], fb_hi, facc[fm][fn]);
                    wmma::mma_sync(facc[fm][fn], fa_hi[fm], fb_lo, facc[fm][fn]);
                    wmma::mma_sync(facc[fm][fn], fa_lo[fm], fb_hi, facc[fm][fn]);
                }
            }
        }
        __syncthreads();
    }

    // epilogue: stage per-warp through smem, emit fp16 (half2 stores)
    float* st = &Stage[wrp * 256];
    #pragma unroll
    for (int fm = 0; fm < 2; fm++)
        #pragma unroll
        for (int fn = 0; fn < WN; fn++) {
            wmma::store_matrix_sync(st, facc[fm][fn], 16, wmma::mem_row_major);
            __syncwarp();
            int rbase = rows0 + warp_m * 32 + fm * 16;
            int cbase = warp_n * (DOUT / 2) + fn * 16;
            #pragma unroll
            for (int q = lane; q < 128; q += 32) {     // 128 half2 per 16x16 tile
                int r = q >> 3, c2 = q & 7;
                int gr = rbase + r;
                if (gr < n) {
                    __half2 hv = __floats2half2_rn(st[r * 16 + c2 * 2],
                                                   st[r * 16 + c2 * 2 + 1]);
                    *(__half2*)&H[(size_t)gr * DOUT + cbase + c2 * 2] = hv;
                }
            }
            __syncwarp();
        }
}

// ---------------- sparse aggregation (one warp per dst, fp16 gather) --------
// out[d,:] = post( norm_dst[d] * sum_{s in N(d)} H[s,:] + b ), fp32 accum.
template <int D, bool ACT>
__global__ void __launch_bounds__(256) k_agg(
    const float* __restrict__ bias, int outSel, float* __restrict__ outExt, int n)
{
    const __half* __restrict__ H = g_bufH;
    float* __restrict__ out = (outSel == 0) ? outExt : g_bufA;

    int gw = (blockIdx.x * blockDim.x + threadIdx.x) >> 5;
    int lane = threadIdx.x & 31;
    if (gw >= n) return;

    int beg = g_rowptr[gw];
    int end = g_rowptr[gw + 1];
    float4 acc = make_float4(0.f, 0.f, 0.f, 0.f);

    for (int e = beg; e < end; e += 32) {
        int m = end - e; if (m > 32) m = 32;
        int idx = (lane < m) ? g_col[e + lane] : 0;
        for (int j = 0; j < m; j++) {
            int s = __shfl_sync(0xffffffffu, idx, j);
            if (D == 128) {
                float2 raw = *(const float2*)&H[(size_t)s * 128 + lane * 4];
                __half2 h0 = *(__half2*)&raw.x;
                __half2 h1 = *(__half2*)&raw.y;
                float2 f0 = __half22float2(h0);
                float2 f1 = __half22float2(h1);
                acc.x += f0.x; acc.y += f0.y; acc.z += f1.x; acc.w += f1.y;
            } else {
                __half2 h = *(const __half2*)&H[(size_t)s * 64 + lane * 2];
                float2 f = __half22float2(h);
                acc.x += f.x; acc.y += f.y;
            }
        }
    }

    float nd = g_norm_dst[gw];
    if (D == 128) {
        float4 bb = *(const float4*)&bias[lane * 4];
        float4 r;
        r.x = fmaf(acc.x, nd, bb.x);
        r.y = fmaf(acc.y, nd, bb.y);
        r.z = fmaf(acc.z, nd, bb.z);
        r.w = fmaf(acc.w, nd, bb.w);
        if (ACT) { r.x = tanhf(r.x); r.y = tanhf(r.y);
                   r.z = tanhf(r.z); r.w = tanhf(r.w); }
        *(float4*)&out[(size_t)gw * 128 + lane * 4] = r;
    } else {
        float2 bb = *(const float2*)&bias[lane * 2];
        float2 r;
        r.x = fmaf(acc.x, nd, bb.x);
        r.y = fmaf(acc.y, nd, bb.y);
        if (ACT) { r.x = tanhf(r.x); r.y = tanhf(r.y); }
        *(float2*)&out[(size_t)gw * 64 + lane * 2] = r;
    }
}

// ---------------- launch ----------------------------------------------------

extern "C" void kernel_launch(void* const* d_in, const int* in_sizes, int n_in,
                              void* d_out, int out_size)
{
    const float* feat = (const float*)d_in[0];
    const void*  ei   = d_in[1];
    const float* W0 = (const float*)d_in[2]; const float* b0 = (const float*)d_in[3];
    const float* W1 = (const float*)d_in[4]; const float* b1 = (const float*)d_in[5];
    const float* W2 = (const float*)d_in[6]; const float* b2 = (const float*)d_in[7];
    const float* W3 = (const float*)d_in[8]; const float* b3 = (const float*)d_in[9];

    int N = in_sizes[0] / 128;
    int E = in_sizes[1] / 2;
    float* out = (float*)d_out;

    int nodeBlocks = (N + 255) / 256;
    int wBlocks = (57344 + 255) / 256;

    // #1..#3: everything gemm0 needs (norm_src)
    k_zero     <<<nodeBlocks + wBlocks, 256>>>(ei, E, N, W0, W1, W2, W3);
    k_degree   <<<(E + 255) / 256, 256>>>(ei, E);
    k_scan_norm<<<(N + 1023) / 1024, 1024>>>(N);

    int gemmGrid = (N + 127) / 128;
    int aggGrid  = (N * 32 + 255) / 256;

    // #4: layer-0 GEMM (profiled launch)
    k_gemm_mma<128><<<gemmGrid, 256>>>(0, feat, 0, N);

    // #5,#6: finish CSR (needed only by k_agg)
    k_scan_add<<<(N + 255) / 256, 256>>>(N, E);
    k_fill    <<<(E + 255) / 256, 256>>>(ei, E);

    // remaining layers (X ping-pongs entirely through g_bufA; H is fp16)
    k_agg<128, true><<<aggGrid, 256>>>(b0, 1, nullptr, N);
    k_gemm_mma<128><<<gemmGrid, 256>>>(1, nullptr, 16384, N);
    k_agg<128, true><<<aggGrid, 256>>>(b1, 1, nullptr, N);
    k_gemm_mma<128><<<gemmGrid, 256>>>(1, nullptr, 32768, N);
    k_agg<128, true><<<aggGrid, 256>>>(b2, 1, nullptr, N);
    k_gemm_mma<64><<<gemmGrid, 256>>>(1, nullptr, 49152, N);
    k_agg<64, false><<<aggGrid, 256>>>(b3, 0, out, N);
}